// round 1
// baseline (speedup 1.0000x reference)
#include <cuda_runtime.h>
#include <cuda_bf16.h>
#include <math.h>

// ---------------- Model constants ----------------
#define DEPTH   24
#define DM      192       // d_model
#define DI      384       // d_inner
#define DSTATE  16
#define DTRANK  12
#define DCONV   4
#define LSEQ    401       // NP+1
#define NB      4         // batch
#define MTOK    (NB*LSEQ) // 1604
#define DXP     (DTRANK + 2*DSTATE) // 44

// ---------------- Scratch (device globals; no allocation) ----------------
__device__ float g_hidden  [MTOK*DM];
__device__ float g_residual[MTOK*DM];
__device__ float g_hnorm   [MTOK*DM];
__device__ float g_xz      [MTOK*2*DI];       // [:,0:384]=xx, [:,384:768]=z
__device__ float g_xconv   [2*MTOK*DI];       // per dir
__device__ float g_dt      [2*MTOK*DI];
__device__ float g_Bm      [2*MTOK*DSTATE];
__device__ float g_Cm      [2*MTOK*DSTATE];
__device__ float g_y       [2*MTOK*DI];       // gated outputs per dir

// ---------------- Patch embed + cls + pos ----------------
__global__ void k_patch(const float* __restrict__ x, const float* __restrict__ pe_w,
                        const float* __restrict__ pe_b, const float* __restrict__ cls,
                        const float* __restrict__ pos)
{
    int p = blockIdx.x;          // 0..399
    int b = blockIdx.y;          // 0..3
    int tid = threadIdx.x;       // 256
    __shared__ float sp[256];
    int ph = p / 200, pw = p % 200;
    int i = tid >> 4, j = tid & 15;
    sp[tid] = x[b*32*3200 + (ph*16 + i)*3200 + pw*16 + j];
    __syncthreads();
    if (tid < DM) {
        int c = tid;
        const float* w = pe_w + c*256;
        float acc = pe_b[c];
        #pragma unroll 8
        for (int k = 0; k < 256; k++) acc += sp[k]*w[k];
        int t = p + 1;
        float v = acc + pos[t*DM + c];
        int m = b*LSEQ + t;
        g_hidden[m*DM + c] = v;
        g_residual[m*DM + c] = v;
        if (p == 0) {
            float cv = cls[c] + pos[c];
            int m0 = b*LSEQ;
            g_hidden[m0*DM + c] = cv;
            g_residual[m0*DM + c] = cv;
        }
    }
}

// ---------------- residual += hidden ; hnorm = rmsnorm(residual)*w ----------------
__global__ void k_prenorm(const float* __restrict__ norm_w)
{
    int warp = threadIdx.x >> 5, lane = threadIdx.x & 31;
    int m = blockIdx.x*8 + warp;
    if (m >= MTOK) return;
    float r[6]; float ss = 0.f;
    #pragma unroll
    for (int u = 0; u < 6; u++) {
        int c = lane + u*32;
        float v = g_residual[m*DM + c] + g_hidden[m*DM + c];
        r[u] = v; ss += v*v;
        g_residual[m*DM + c] = v;
    }
    #pragma unroll
    for (int o = 16; o; o >>= 1) ss += __shfl_xor_sync(~0u, ss, o);
    float rstd = rsqrtf(ss*(1.f/DM) + 1e-5f);
    #pragma unroll
    for (int u = 0; u < 6; u++) {
        int c = lane + u*32;
        g_hnorm[m*DM + c] = r[u]*rstd*norm_w[c];
    }
}

// ---------------- GEMM: C[m,n] = sum_k A[m,k]*W[n,k] ----------------
// MODE 0: A=g_hnorm (K=192), C=g_xz (N=768)
// MODE 1: A=g_y[0]+g_y[1] (K=384), C=g_hidden (N=192)
template<int MODE>
__global__ void k_gemm(const float* __restrict__ W)
{
    const int K = (MODE == 0) ? DM : DI;
    const int N = (MODE == 0) ? 2*DI : DM;
    __shared__ float As[16][68];
    __shared__ float Ws[16][68];
    int tid = threadIdx.x;             // 256
    int m0 = blockIdx.x*64, n0 = blockIdx.y*64;
    int r = tid >> 2, kq = tid & 3;
    int tx = tid & 15, ty = tid >> 4;
    float acc[4][4] = {};
    for (int k0 = 0; k0 < K; k0 += 16) {
        // A tile
        {
            int m = m0 + r;
            float4 v = make_float4(0.f, 0.f, 0.f, 0.f);
            if (m < MTOK) {
                if (MODE == 0) {
                    v = *(const float4*)(g_hnorm + m*K + k0 + kq*4);
                } else {
                    float4 a = *(const float4*)(g_y + m*K + k0 + kq*4);
                    float4 b2 = *(const float4*)(g_y + MTOK*DI + m*K + k0 + kq*4);
                    v = make_float4(a.x + b2.x, a.y + b2.y, a.z + b2.z, a.w + b2.w);
                }
            }
            As[kq*4 + 0][r] = v.x; As[kq*4 + 1][r] = v.y;
            As[kq*4 + 2][r] = v.z; As[kq*4 + 3][r] = v.w;
            float4 w4 = *(const float4*)(W + (n0 + r)*K + k0 + kq*4);
            Ws[kq*4 + 0][r] = w4.x; Ws[kq*4 + 1][r] = w4.y;
            Ws[kq*4 + 2][r] = w4.z; Ws[kq*4 + 3][r] = w4.w;
        }
        __syncthreads();
        #pragma unroll
        for (int k = 0; k < 16; k++) {
            float4 a = *(const float4*)&As[k][ty*4];
            float4 b = *(const float4*)&Ws[k][tx*4];
            float av[4] = {a.x, a.y, a.z, a.w};
            float bv[4] = {b.x, b.y, b.z, b.w};
            #pragma unroll
            for (int i2 = 0; i2 < 4; i2++)
                #pragma unroll
                for (int j2 = 0; j2 < 4; j2++)
                    acc[i2][j2] = fmaf(av[i2], bv[j2], acc[i2][j2]);
        }
        __syncthreads();
    }
    float* C = (MODE == 0) ? g_xz : g_hidden;
    #pragma unroll
    for (int i2 = 0; i2 < 4; i2++) {
        int m = m0 + ty*4 + i2;
        if (m < MTOK) {
            #pragma unroll
            for (int j2 = 0; j2 < 4; j2++)
                C[m*N + n0 + tx*4 + j2] = acc[i2][j2];
        }
    }
}

// ---------------- conv + silu + xproj + dtproj (both dirs) ----------------
__global__ void k_convx(const float* __restrict__ cw, const float* __restrict__ cb,
                        const float* __restrict__ xpw, const float* __restrict__ dtw,
                        const float* __restrict__ dtb)
{
    int t = blockIdx.x, b = blockIdx.y, dir = blockIdx.z;
    int tid = threadIdx.x; // 128
    __shared__ float xc[DI];
    __shared__ float dbl[DXP];
    int mbase = b*LSEQ;
    int midx = dir*MTOK + mbase + t;

    for (int d = tid; d < DI; d += 128) {
        float acc = cb[d];
        #pragma unroll
        for (int k = 0; k < 4; k++) {
            int tt = (dir == 0) ? (t - 3 + k) : (t + 3 - k);
            if (tt >= 0 && tt <= LSEQ - 2 + 1 - 1) { // 0..400
                acc = fmaf(g_xz[(mbase + tt)*2*DI + d], cw[d*4 + k], acc);
            }
        }
        float v = acc / (1.f + __expf(-acc)); // silu
        xc[d] = v;
        g_xconv[midx*DI + d] = v;
    }
    __syncthreads();

    int warp = tid >> 5, lane = tid & 31;
    for (int jj = 0; jj < 11; jj++) {
        int j = warp*11 + jj;     // 4 warps * 11 = 44
        float s = 0.f;
        const float* wr = xpw + j*DI;
        #pragma unroll
        for (int u = 0; u < 12; u++) s = fmaf(xc[lane + u*32], wr[lane + u*32], s);
        #pragma unroll
        for (int o = 16; o; o >>= 1) s += __shfl_xor_sync(~0u, s, o);
        if (lane == 0) dbl[j] = s;
    }
    __syncthreads();

    if (tid < DSTATE) {
        g_Bm[midx*DSTATE + tid] = dbl[DTRANK + tid];
        g_Cm[midx*DSTATE + tid] = dbl[DTRANK + DSTATE + tid];
    }
    for (int d = tid; d < DI; d += 128) {
        float s = dtb[d];
        const float* wr = dtw + d*DTRANK;
        #pragma unroll
        for (int r2 = 0; r2 < DTRANK; r2++) s = fmaf(dbl[r2], wr[r2], s);
        float sp = (s > 20.f) ? s : log1pf(__expf(s));
        g_dt[midx*DI + d] = sp;
    }
}

// ---------------- selective scan + gate (both dirs via grid.z) ----------------
__global__ void k_scan(const float* __restrict__ Alog_f, const float* __restrict__ Alog_b,
                       const float* __restrict__ Dp)
{
    int cblk = blockIdx.x;  // 0..23 (16 channels each)
    int b = blockIdx.y;
    int dir = blockIdx.z;
    int tid = threadIdx.x;  // 256 = 8 warps
    int warp = tid >> 5, lane = tid & 31;
    int d = cblk*16 + warp*2 + (lane >> 4);
    int n = lane & 15;
    const float* Alog = dir ? Alog_b : Alog_f;
    float A  = -__expf(Alog[d*DSTATE + n]);
    float Dk = Dp[d];
    int mbase = b*LSEQ;
    int m  = dir ? (mbase + LSEQ - 1) : mbase;
    int dm = dir ? -1 : 1;
    int gi = dir*MTOK + m;

    float dt = g_dt[gi*DI + d];
    float xv = g_xconv[gi*DI + d];
    float Bn = g_Bm[gi*DSTATE + n];
    float Cn = g_Cm[gi*DSTATE + n];
    float h = 0.f;

    for (int s = 0; s < LSEQ; s++) {
        int gin = gi + dm;
        float dt2 = 0.f, xv2 = 0.f, Bn2 = 0.f, Cn2 = 0.f;
        if (s < LSEQ - 1) {
            dt2 = g_dt[gin*DI + d];
            xv2 = g_xconv[gin*DI + d];
            Bn2 = g_Bm[gin*DSTATE + n];
            Cn2 = g_Cm[gin*DSTATE + n];
        }
        float dA = __expf(dt*A);
        h = fmaf(dA, h, dt*xv*Bn);
        float p = h*Cn;
        p += __shfl_xor_sync(~0u, p, 1);
        p += __shfl_xor_sync(~0u, p, 2);
        p += __shfl_xor_sync(~0u, p, 4);
        p += __shfl_xor_sync(~0u, p, 8);
        if (n == 0) {
            float z = g_xz[m*2*DI + DI + d];
            float y = fmaf(xv, Dk, p);
            g_y[gi*DI + d] = y * (z / (1.f + __expf(-z)));
        }
        m  += dm;
        gi  = gin;
        dt = dt2; xv = xv2; Bn = Bn2; Cn = Cn2;
    }
}

// ---------------- final norm + head (cls token only) ----------------
__global__ void k_head(const float* __restrict__ nfw, const float* __restrict__ hw,
                       const float* __restrict__ hb, float* __restrict__ out)
{
    int b = blockIdx.x;
    int tid = threadIdx.x; // 192
    __shared__ float rn[DM];
    __shared__ float red[6];
    int m = b*LSEQ;
    float v = g_residual[m*DM + tid] + g_hidden[m*DM + tid];
    float ss = v*v;
    #pragma unroll
    for (int o = 16; o; o >>= 1) ss += __shfl_xor_sync(~0u, ss, o);
    if ((tid & 31) == 0) red[tid >> 5] = ss;
    __syncthreads();
    float tot = red[0] + red[1] + red[2] + red[3] + red[4] + red[5];
    float rstd = rsqrtf(tot*(1.f/DM) + 1e-5f);
    rn[tid] = v*rstd*nfw[tid];
    __syncthreads();
    if (tid < 22) {
        float s = hb[tid];
        const float* wr = hw + tid*DM;
        #pragma unroll 4
        for (int k = 0; k < DM; k++) s = fmaf(rn[k], wr[k], s);
        out[b*22 + tid] = s;
    }
}

// ---------------- launcher ----------------
extern "C" void kernel_launch(void* const* d_in, const int* in_sizes, int n_in,
                              void* d_out, int out_size)
{
    const float* x         = (const float*)d_in[0];
    const float* pe_w      = (const float*)d_in[1];
    const float* pe_b      = (const float*)d_in[2];
    const float* cls_token = (const float*)d_in[3];
    const float* pos_embed = (const float*)d_in[4];
    const float* norm_w    = (const float*)d_in[5];
    const float* in_proj_w = (const float*)d_in[6];
    const float* cw        = (const float*)d_in[7];
    const float* cb        = (const float*)d_in[8];
    const float* xproj_w   = (const float*)d_in[9];
    const float* dtproj_w  = (const float*)d_in[10];
    const float* dtproj_b  = (const float*)d_in[11];
    const float* A_log     = (const float*)d_in[12];
    const float* A_b_log   = (const float*)d_in[13];
    const float* Dp        = (const float*)d_in[14];
    const float* outproj_w = (const float*)d_in[15];
    const float* norm_f_w  = (const float*)d_in[16];
    const float* head_w    = (const float*)d_in[17];
    const float* head_b    = (const float*)d_in[18];
    float* out = (float*)d_out;

    k_patch<<<dim3(400, NB), 256>>>(x, pe_w, pe_b, cls_token, pos_embed);

    for (int l = 0; l < DEPTH; l++) {
        k_prenorm<<<(MTOK + 7)/8, 256>>>(norm_w + l*DM);
        k_gemm<0><<<dim3((MTOK + 63)/64, (2*DI)/64), 256>>>(in_proj_w + (size_t)l*2*DI*DM);
        k_convx<<<dim3(LSEQ, NB, 2), 128>>>(cw + l*DI*DCONV, cb + l*DI,
                                            xproj_w + l*DXP*DI,
                                            dtproj_w + l*DI*DTRANK, dtproj_b + l*DI);
        k_scan<<<dim3(DI/16, NB, 2), 256>>>(A_log + (size_t)l*DI*DSTATE,
                                            A_b_log + (size_t)l*DI*DSTATE,
                                            Dp + l*DI);
        k_gemm<1><<<dim3((MTOK + 63)/64, DM/64), 256>>>(outproj_w + (size_t)l*DM*DI);
    }

    k_head<<<NB, DM>>>(norm_f_w, head_w, head_b, out);
}

// round 4
// speedup vs baseline: 2.3372x; 2.3372x over previous
#include <cuda_runtime.h>
#include <cuda_bf16.h>
#include <math.h>

// ---------------- Model constants ----------------
#define DEPTH   24
#define DM      192       // d_model
#define DI      384       // d_inner
#define DSTATE  16
#define DTRANK  12
#define DCONV   4
#define LSEQ    401       // NP+1
#define NB      4         // batch
#define MTOK    (NB*LSEQ) // 1604
#define DXP     (DTRANK + 2*DSTATE) // 44
#define CT      64        // scan chunk length

// ---------------- Scratch (device globals; no allocation) ----------------
__device__ float g_hidden  [MTOK*DM];
__device__ float g_residual[MTOK*DM];
__device__ float g_hnorm   [MTOK*DM];
__device__ float g_xz      [MTOK*2*DI];       // [:,0:384]=xx, [:,384:768]=z
__device__ float g_xconv   [2*MTOK*DI];       // per dir, silu(conv(x))
__device__ float g_dbl     [2*MTOK*DXP];      // xproj output [dt_r(12), B(16), C(16)]
__device__ float g_y       [2*MTOK*DI];       // gated outputs per dir

// ---------------- Patch embed + cls + pos ----------------
__global__ void k_patch(const float* __restrict__ x, const float* __restrict__ pe_w,
                        const float* __restrict__ pe_b, const float* __restrict__ cls,
                        const float* __restrict__ pos)
{
    int p = blockIdx.x;          // 0..399
    int b = blockIdx.y;          // 0..3
    int tid = threadIdx.x;       // 256
    __shared__ float sp[256];
    int ph = p / 200, pw = p % 200;
    int i = tid >> 4, j = tid & 15;
    sp[tid] = x[b*32*3200 + (ph*16 + i)*3200 + pw*16 + j];
    __syncthreads();
    if (tid < DM) {
        int c = tid;
        const float* w = pe_w + c*256;
        float acc = pe_b[c];
        #pragma unroll 8
        for (int k = 0; k < 256; k++) acc += sp[k]*w[k];
        int t = p + 1;
        float v = acc + pos[t*DM + c];
        int m = b*LSEQ + t;
        g_hidden[m*DM + c] = v;
        g_residual[m*DM + c] = v;
        if (p == 0) {
            float cv = cls[c] + pos[c];
            int m0 = b*LSEQ;
            g_hidden[m0*DM + c] = cv;
            g_residual[m0*DM + c] = cv;
        }
    }
}

// ---------------- residual += hidden ; hnorm = rmsnorm(residual)*w ----------------
__global__ void k_prenorm(const float* __restrict__ norm_w)
{
    int warp = threadIdx.x >> 5, lane = threadIdx.x & 31;
    int m = blockIdx.x*8 + warp;
    if (m >= MTOK) return;
    float r[6]; float ss = 0.f;
    #pragma unroll
    for (int u = 0; u < 6; u++) {
        int c = lane + u*32;
        float v = g_residual[m*DM + c] + g_hidden[m*DM + c];
        r[u] = v; ss += v*v;
        g_residual[m*DM + c] = v;
    }
    #pragma unroll
    for (int o = 16; o; o >>= 1) ss += __shfl_xor_sync(~0u, ss, o);
    float rstd = rsqrtf(ss*(1.f/DM) + 1e-5f);
    #pragma unroll
    for (int u = 0; u < 6; u++) {
        int c = lane + u*32;
        g_hnorm[m*DM + c] = r[u]*rstd*norm_w[c];
    }
}

// ---------------- GEMM: C[m,n] = sum_k A[m,k]*W[n,k] ----------------
// MODE 0: A=g_hnorm  (M=1604, K=192), C=g_xz   (N=768)
// MODE 1: A=g_y0+g_y1(M=1604, K=384), C=g_hidden (N=192)
// MODE 2: A=g_xconv  (M=3208, K=384), C=g_dbl  (N=44)
template<int MODE>
__global__ void k_gemm(const float* __restrict__ W)
{
    constexpr int K = (MODE == 0) ? DM : DI;
    constexpr int N = (MODE == 0) ? 2*DI : ((MODE == 1) ? DM : DXP);
    constexpr int M = (MODE == 2) ? 2*MTOK : MTOK;
    __shared__ float As[16][68];
    __shared__ float Ws[16][68];
    int tid = threadIdx.x;             // 256
    int m0 = blockIdx.x*64, n0 = blockIdx.y*64;
    int r = tid >> 2, kq = tid & 3;
    int tx = tid & 15, ty = tid >> 4;
    float acc[4][4] = {};
    for (int k0 = 0; k0 < K; k0 += 16) {
        {
            int m = m0 + r;
            float4 v = make_float4(0.f, 0.f, 0.f, 0.f);
            if (m < M) {
                if (MODE == 0) {
                    v = *(const float4*)(g_hnorm + m*K + k0 + kq*4);
                } else if (MODE == 1) {
                    float4 a = *(const float4*)(g_y + m*K + k0 + kq*4);
                    float4 b2 = *(const float4*)(g_y + MTOK*DI + m*K + k0 + kq*4);
                    v = make_float4(a.x + b2.x, a.y + b2.y, a.z + b2.z, a.w + b2.w);
                } else {
                    v = *(const float4*)(g_xconv + m*K + k0 + kq*4);
                }
            }
            As[kq*4 + 0][r] = v.x; As[kq*4 + 1][r] = v.y;
            As[kq*4 + 2][r] = v.z; As[kq*4 + 3][r] = v.w;
            int wrow = n0 + r; if (wrow >= N) wrow = 0;
            float4 w4 = *(const float4*)(W + wrow*K + k0 + kq*4);
            Ws[kq*4 + 0][r] = w4.x; Ws[kq*4 + 1][r] = w4.y;
            Ws[kq*4 + 2][r] = w4.z; Ws[kq*4 + 3][r] = w4.w;
        }
        __syncthreads();
        #pragma unroll
        for (int k = 0; k < 16; k++) {
            float4 a = *(const float4*)&As[k][ty*4];
            float4 b = *(const float4*)&Ws[k][tx*4];
            float av[4] = {a.x, a.y, a.z, a.w};
            float bv[4] = {b.x, b.y, b.z, b.w};
            #pragma unroll
            for (int i2 = 0; i2 < 4; i2++)
                #pragma unroll
                for (int j2 = 0; j2 < 4; j2++)
                    acc[i2][j2] = fmaf(av[i2], bv[j2], acc[i2][j2]);
        }
        __syncthreads();
    }
    float* C = (MODE == 0) ? g_xz : ((MODE == 1) ? g_hidden : g_dbl);
    #pragma unroll
    for (int i2 = 0; i2 < 4; i2++) {
        int m = m0 + ty*4 + i2;
        if (m < M) {
            #pragma unroll
            for (int j2 = 0; j2 < 4; j2++) {
                int n = n0 + tx*4 + j2;
                if (N % 64 == 0 || n < N) C[m*N + n] = acc[i2][j2];
            }
        }
    }
}

// ---------------- causal dwconv + silu, both dirs ----------------
__global__ void k_conv(const float* __restrict__ cw, const float* __restrict__ cb)
{
    int t = blockIdx.x, b = blockIdx.y;
    int d = threadIdx.x;              // 384
    float w0 = cw[d*4+0], w1 = cw[d*4+1], w2 = cw[d*4+2], w3 = cw[d*4+3];
    float bias = cb[d];
    int rowbase = b*LSEQ;
    // forward dir: taps t-3..t with weights w0..w3
    float accf = bias;
    if (t-3 >= 0) accf = fmaf(g_xz[(rowbase + t-3)*2*DI + d], w0, accf);
    if (t-2 >= 0) accf = fmaf(g_xz[(rowbase + t-2)*2*DI + d], w1, accf);
    if (t-1 >= 0) accf = fmaf(g_xz[(rowbase + t-1)*2*DI + d], w2, accf);
    accf = fmaf(g_xz[(rowbase + t)*2*DI + d], w3, accf);
    g_xconv[(rowbase + t)*DI + d] = accf / (1.f + __expf(-accf));
    // backward dir: taps t+3..t with weights w0..w3
    float accb = bias;
    if (t+3 <= LSEQ-1) accb = fmaf(g_xz[(rowbase + t+3)*2*DI + d], w0, accb);
    if (t+2 <= LSEQ-1) accb = fmaf(g_xz[(rowbase + t+2)*2*DI + d], w1, accb);
    if (t+1 <= LSEQ-1) accb = fmaf(g_xz[(rowbase + t+1)*2*DI + d], w2, accb);
    accb = fmaf(g_xz[(rowbase + t)*2*DI + d], w3, accb);
    g_xconv[(MTOK + rowbase + t)*DI + d] = accb / (1.f + __expf(-accb));
}

// ---------------- selective scan + gate (smem-chunked) ----------------
__global__ void k_scan(const float* __restrict__ Alog_f, const float* __restrict__ Alog_b,
                       const float* __restrict__ Dp, const float* __restrict__ dtw,
                       const float* __restrict__ dtb)
{
    int cblk = blockIdx.x;  // 0..23 (16 channels each)
    int b = blockIdx.y;
    int dir = blockIdx.z;
    int tid = threadIdx.x;  // 256 = 8 warps
    int warp = tid >> 5, lane = tid & 31;
    int dloc = warp*2 + (lane >> 4);
    int d = cblk*16 + dloc;
    int n = lane & 15;

    __shared__ float s_dtw[16*12];
    __shared__ float s_dtb[16];
    // 0=dt 1=xv 2=B 3=C 4=z
    __shared__ float sbuf[2][5][CT*16];

    if (tid < 192) s_dtw[tid] = dtw[(cblk*16 + tid/12)*DTRANK + (tid % 12)];
    if (tid < 16)  s_dtb[tid] = dtb[cblk*16 + tid];

    const float* Alog = dir ? Alog_b : Alog_f;
    float A  = -__expf(Alog[d*DSTATE + n]);
    float Dk = Dp[d];
    int rowbase = b*LSEQ;
    __syncthreads();

    // ---- staging lambda: chunk starting at t0 into buffer bf ----
    auto stage = [&](int t0, int bf) {
        #pragma unroll
        for (int it = 0; it < 4; it++) {
            int idx = tid + it*256;           // 0..1023
            int tt = t0 + (idx >> 4);
            int j = idx & 15;
            if (tt < LSEQ) {
                int m = dir ? (LSEQ-1 - tt) : tt;
                int gi = dir*MTOK + rowbase + m;
                const float* db = g_dbl + gi*DXP;
                float s = s_dtb[j];
                const float* wr = s_dtw + j*12;
                #pragma unroll
                for (int r2 = 0; r2 < DTRANK; r2++) s = fmaf(db[r2], wr[r2], s);
                float sp = (s > 20.f) ? s : log1pf(__expf(s));
                sbuf[bf][0][idx] = sp;
                sbuf[bf][1][idx] = g_xconv[gi*DI + cblk*16 + j];
                sbuf[bf][2][idx] = db[DTRANK + j];
                sbuf[bf][3][idx] = db[DTRANK + DSTATE + j];
                sbuf[bf][4][idx] = g_xz[(rowbase + m)*2*DI + DI + cblk*16 + j];
            }
        }
    };

    stage(0, 0);
    __syncthreads();

    float h = 0.f;
    int nchunks = (LSEQ + CT - 1)/CT;   // 7
    for (int c = 0; c < nchunks; c++) {
        int bf = c & 1;
        int tmax = min(CT, LSEQ - c*CT);
        #pragma unroll 4
        for (int k = 0; k < tmax; k++) {
            int base = k*16;
            float dt = sbuf[bf][0][base + dloc];
            float xv = sbuf[bf][1][base + dloc];
            float Bn = sbuf[bf][2][base + n];
            float Cn = sbuf[bf][3][base + n];
            float dA = __expf(dt*A);
            h = fmaf(dA, h, dt*xv*Bn);
            float p = h*Cn;
            p += __shfl_xor_sync(~0u, p, 1);
            p += __shfl_xor_sync(~0u, p, 2);
            p += __shfl_xor_sync(~0u, p, 4);
            p += __shfl_xor_sync(~0u, p, 8);
            if (n == 0) {
                float z = sbuf[bf][4][base + dloc];
                float y = fmaf(xv, Dk, p);
                int t = c*CT + k;
                int m = dir ? (LSEQ-1 - t) : t;
                int gi = dir*MTOK + rowbase + m;
                g_y[gi*DI + d] = y * (z / (1.f + __expf(-z)));
            }
        }
        if ((c+1) < nchunks) stage((c+1)*CT, bf^1);
        __syncthreads();
    }
}

// ---------------- final norm + head (cls token only) ----------------
__global__ void k_head(const float* __restrict__ nfw, const float* __restrict__ hw,
                       const float* __restrict__ hb, float* __restrict__ out)
{
    int b = blockIdx.x;
    int tid = threadIdx.x; // 192
    __shared__ float rn[DM];
    __shared__ float red[6];
    int m = b*LSEQ;
    float v = g_residual[m*DM + tid] + g_hidden[m*DM + tid];
    float ss = v*v;
    #pragma unroll
    for (int o = 16; o; o >>= 1) ss += __shfl_xor_sync(~0u, ss, o);
    if ((tid & 31) == 0) red[tid >> 5] = ss;
    __syncthreads();
    float tot = red[0] + red[1] + red[2] + red[3] + red[4] + red[5];
    float rstd = rsqrtf(tot*(1.f/DM) + 1e-5f);
    rn[tid] = v*rstd*nfw[tid];
    __syncthreads();
    if (tid < 22) {
        float s = hb[tid];
        const float* wr = hw + tid*DM;
        #pragma unroll 4
        for (int k = 0; k < DM; k++) s = fmaf(rn[k], wr[k], s);
        out[b*22 + tid] = s;
    }
}

// ---------------- launcher ----------------
extern "C" void kernel_launch(void* const* d_in, const int* in_sizes, int n_in,
                              void* d_out, int out_size)
{
    const float* x         = (const float*)d_in[0];
    const float* pe_w      = (const float*)d_in[1];
    const float* pe_b      = (const float*)d_in[2];
    const float* cls_token = (const float*)d_in[3];
    const float* pos_embed = (const float*)d_in[4];
    const float* norm_w    = (const float*)d_in[5];
    const float* in_proj_w = (const float*)d_in[6];
    const float* cw        = (const float*)d_in[7];
    const float* cb        = (const float*)d_in[8];
    const float* xproj_w   = (const float*)d_in[9];
    const float* dtproj_w  = (const float*)d_in[10];
    const float* dtproj_b  = (const float*)d_in[11];
    const float* A_log     = (const float*)d_in[12];
    const float* A_b_log   = (const float*)d_in[13];
    const float* Dp        = (const float*)d_in[14];
    const float* outproj_w = (const float*)d_in[15];
    const float* norm_f_w  = (const float*)d_in[16];
    const float* head_w    = (const float*)d_in[17];
    const float* head_b    = (const float*)d_in[18];
    float* out = (float*)d_out;

    k_patch<<<dim3(400, NB), 256>>>(x, pe_w, pe_b, cls_token, pos_embed);

    for (int l = 0; l < DEPTH; l++) {
        k_prenorm<<<(MTOK + 7)/8, 256>>>(norm_w + l*DM);
        k_gemm<0><<<dim3((MTOK + 63)/64, (2*DI)/64), 256>>>(in_proj_w + (size_t)l*2*DI*DM);
        k_conv<<<dim3(LSEQ, NB), DI>>>(cw + l*DI*DCONV, cb + l*DI);
        k_gemm<2><<<dim3((2*MTOK + 63)/64, 1), 256>>>(xproj_w + (size_t)l*DXP*DI);
        k_scan<<<dim3(DI/16, NB, 2), 256>>>(A_log + (size_t)l*DI*DSTATE,
                                            A_b_log + (size_t)l*DI*DSTATE,
                                            Dp + l*DI,
                                            dtproj_w + (size_t)l*DI*DTRANK,
                                            dtproj_b + l*DI);
        k_gemm<1><<<dim3((MTOK + 63)/64, DM/64), 256>>>(outproj_w + (size_t)l*DM*DI);
    }

    k_head<<<NB, DM>>>(norm_f_w, head_w, head_b, out);
}

// round 6
// speedup vs baseline: 2.9959x; 1.2819x over previous
#include <cuda_runtime.h>
#include <cuda_bf16.h>
#include <math.h>

// ---------------- Model constants ----------------
#define DEPTH   24
#define DM      192       // d_model
#define DI      384       // d_inner
#define DSTATE  16
#define DTRANK  12
#define DCONV   4
#define LSEQ    401       // NP+1
#define NB      4         // batch
#define MTOK    (NB*LSEQ) // 1604
#define DXP     (DTRANK + 2*DSTATE) // 44
#define CT      24        // scan chunk length

// ---------------- Scratch (device globals; no allocation) ----------------
__device__ float g_hidden  [MTOK*DM];
__device__ float g_residual[MTOK*DM];
__device__ float g_hnorm   [MTOK*DM];
__device__ float g_xz      [MTOK*2*DI];       // [:,0:384]=xx, [:,384:768]=z
__device__ float g_xconv   [2*MTOK*DI];       // per dir, silu(conv(x))
__device__ float g_dbl     [2*MTOK*DXP];      // xproj out [dt_r(12), B(16), C(16)]
__device__ float g_dt      [2*MTOK*DI];       // softplus(dt)
__device__ float g_y       [2*MTOK*DI];       // gated outputs per dir

// ---------------- Patch embed + cls + pos ----------------
__global__ void k_patch(const float* __restrict__ x, const float* __restrict__ pe_w,
                        const float* __restrict__ pe_b, const float* __restrict__ cls,
                        const float* __restrict__ pos)
{
    int p = blockIdx.x;          // 0..399
    int b = blockIdx.y;          // 0..3
    int tid = threadIdx.x;       // 256
    __shared__ float sp[256];
    int ph = p / 200, pw = p % 200;
    int i = tid >> 4, j = tid & 15;
    sp[tid] = x[b*32*3200 + (ph*16 + i)*3200 + pw*16 + j];
    __syncthreads();
    if (tid < DM) {
        int c = tid;
        const float* w = pe_w + c*256;
        float acc = pe_b[c];
        #pragma unroll 8
        for (int k = 0; k < 256; k++) acc += sp[k]*w[k];
        int t = p + 1;
        float v = acc + pos[t*DM + c];
        int m = b*LSEQ + t;
        g_hidden[m*DM + c] = v;
        g_residual[m*DM + c] = v;
        if (p == 0) {
            float cv = cls[c] + pos[c];
            int m0 = b*LSEQ;
            g_hidden[m0*DM + c] = cv;
            g_residual[m0*DM + c] = cv;
        }
    }
}

// ---------------- residual += hidden ; hnorm = rmsnorm(residual)*w ----------------
__global__ void k_prenorm(const float* __restrict__ norm_w)
{
    int warp = threadIdx.x >> 5, lane = threadIdx.x & 31;
    int m = blockIdx.x*8 + warp;
    if (m >= MTOK) return;
    float r[6]; float ss = 0.f;
    #pragma unroll
    for (int u = 0; u < 6; u++) {
        int c = lane + u*32;
        float v = g_residual[m*DM + c] + g_hidden[m*DM + c];
        r[u] = v; ss += v*v;
        g_residual[m*DM + c] = v;
    }
    #pragma unroll
    for (int o = 16; o; o >>= 1) ss += __shfl_xor_sync(~0u, ss, o);
    float rstd = rsqrtf(ss*(1.f/DM) + 1e-5f);
    #pragma unroll
    for (int u = 0; u < 6; u++) {
        int c = lane + u*32;
        g_hnorm[m*DM + c] = r[u]*rstd*norm_w[c];
    }
}

// ---------------- GEMM0: g_xz[1604,768] = g_hnorm[1604,192] @ W[768,192]^T ----------------
// 128x64 tile, 256 thr, 8x4 acc, KT=16, double-buffered
__global__ void k_gemm0(const float* __restrict__ W)
{
    __shared__ float As[2][16][132];
    __shared__ float Ws[2][16][68];
    int tid = threadIdx.x;
    int m0 = blockIdx.x*128, n0 = blockIdx.y*64;
    int arow = tid >> 1, akq = (tid & 1)*2;   // this thread: kq = akq, akq+1
    int wrow = tid >> 2, wkq = tid & 3;
    int tx = tid & 15, ty = tid >> 4;
    float4 pa0, pa1, pw;

    // prologue: tile 0
    {
        int m = m0 + arow;
        if (m < MTOK) {
            pa0 = *(const float4*)(g_hnorm + m*DM + akq*4);
            pa1 = *(const float4*)(g_hnorm + m*DM + akq*4 + 4);
        } else { pa0 = make_float4(0,0,0,0); pa1 = pa0; }
        pw = *(const float4*)(W + (n0 + wrow)*DM + wkq*4);
        As[0][akq*4+0][arow]=pa0.x; As[0][akq*4+1][arow]=pa0.y;
        As[0][akq*4+2][arow]=pa0.z; As[0][akq*4+3][arow]=pa0.w;
        As[0][akq*4+4][arow]=pa1.x; As[0][akq*4+5][arow]=pa1.y;
        As[0][akq*4+6][arow]=pa1.z; As[0][akq*4+7][arow]=pa1.w;
        Ws[0][wkq*4+0][wrow]=pw.x;  Ws[0][wkq*4+1][wrow]=pw.y;
        Ws[0][wkq*4+2][wrow]=pw.z;  Ws[0][wkq*4+3][wrow]=pw.w;
    }
    __syncthreads();

    float acc[8][4] = {};
    const int NK = DM/16;  // 12
    for (int kt = 0; kt < NK; kt++) {
        if (kt + 1 < NK) {
            int k0 = (kt+1)*16;
            int m = m0 + arow;
            if (m < MTOK) {
                pa0 = *(const float4*)(g_hnorm + m*DM + k0 + akq*4);
                pa1 = *(const float4*)(g_hnorm + m*DM + k0 + akq*4 + 4);
            } else { pa0 = make_float4(0,0,0,0); pa1 = pa0; }
            pw = *(const float4*)(W + (n0 + wrow)*DM + k0 + wkq*4);
        }
        int buf = kt & 1;
        #pragma unroll
        for (int k = 0; k < 16; k++) {
            float4 bv = *(const float4*)&Ws[buf][k][tx*4];
            float4 a0 = *(const float4*)&As[buf][k][ty*8];
            float4 a1 = *(const float4*)&As[buf][k][ty*8+4];
            float av[8] = {a0.x,a0.y,a0.z,a0.w,a1.x,a1.y,a1.z,a1.w};
            float bw[4] = {bv.x,bv.y,bv.z,bv.w};
            #pragma unroll
            for (int i2 = 0; i2 < 8; i2++)
                #pragma unroll
                for (int j2 = 0; j2 < 4; j2++)
                    acc[i2][j2] = fmaf(av[i2], bw[j2], acc[i2][j2]);
        }
        if (kt + 1 < NK) {
            int bn = buf ^ 1;
            As[bn][akq*4+0][arow]=pa0.x; As[bn][akq*4+1][arow]=pa0.y;
            As[bn][akq*4+2][arow]=pa0.z; As[bn][akq*4+3][arow]=pa0.w;
            As[bn][akq*4+4][arow]=pa1.x; As[bn][akq*4+5][arow]=pa1.y;
            As[bn][akq*4+6][arow]=pa1.z; As[bn][akq*4+7][arow]=pa1.w;
            Ws[bn][wkq*4+0][wrow]=pw.x;  Ws[bn][wkq*4+1][wrow]=pw.y;
            Ws[bn][wkq*4+2][wrow]=pw.z;  Ws[bn][wkq*4+3][wrow]=pw.w;
        }
        __syncthreads();
    }
    #pragma unroll
    for (int i2 = 0; i2 < 8; i2++) {
        int m = m0 + ty*8 + i2;
        if (m < MTOK) {
            float4 v = make_float4(acc[i2][0], acc[i2][1], acc[i2][2], acc[i2][3]);
            *(float4*)(g_xz + m*2*DI + n0 + tx*4) = v;
        }
    }
}

// ---------------- GEMM1: g_hidden[1604,192] = (y0+y1)[1604,384] @ W[192,384]^T ----------------
// 64x64 tile, 256 thr, 4x4 acc, KT=32, double-buffered
__global__ void k_gemm1(const float* __restrict__ W)
{
    __shared__ float As[2][32][68];
    __shared__ float Ws[2][32][68];
    int tid = threadIdx.x;
    int m0 = blockIdx.x*64, n0 = blockIdx.y*64;
    int row = tid >> 2, kq0 = (tid & 3)*2;    // kq = kq0, kq0+1 of 8
    int tx = tid & 15, ty = tid >> 4;
    float4 pa0, pa1, pw0, pw1;

    {
        int m = m0 + row;
        if (m < MTOK) {
            float4 a = *(const float4*)(g_y + m*DI + kq0*4);
            float4 b = *(const float4*)(g_y + (size_t)MTOK*DI + m*DI + kq0*4);
            pa0 = make_float4(a.x+b.x, a.y+b.y, a.z+b.z, a.w+b.w);
            a = *(const float4*)(g_y + m*DI + kq0*4 + 4);
            b = *(const float4*)(g_y + (size_t)MTOK*DI + m*DI + kq0*4 + 4);
            pa1 = make_float4(a.x+b.x, a.y+b.y, a.z+b.z, a.w+b.w);
        } else { pa0 = make_float4(0,0,0,0); pa1 = pa0; }
        pw0 = *(const float4*)(W + (n0 + row)*DI + kq0*4);
        pw1 = *(const float4*)(W + (n0 + row)*DI + kq0*4 + 4);
        As[0][kq0*4+0][row]=pa0.x; As[0][kq0*4+1][row]=pa0.y;
        As[0][kq0*4+2][row]=pa0.z; As[0][kq0*4+3][row]=pa0.w;
        As[0][kq0*4+4][row]=pa1.x; As[0][kq0*4+5][row]=pa1.y;
        As[0][kq0*4+6][row]=pa1.z; As[0][kq0*4+7][row]=pa1.w;
        Ws[0][kq0*4+0][row]=pw0.x; Ws[0][kq0*4+1][row]=pw0.y;
        Ws[0][kq0*4+2][row]=pw0.z; Ws[0][kq0*4+3][row]=pw0.w;
        Ws[0][kq0*4+4][row]=pw1.x; Ws[0][kq0*4+5][row]=pw1.y;
        Ws[0][kq0*4+6][row]=pw1.z; Ws[0][kq0*4+7][row]=pw1.w;
    }
    __syncthreads();

    float acc[4][4] = {};
    const int NK = DI/32;  // 12
    for (int kt = 0; kt < NK; kt++) {
        if (kt + 1 < NK) {
            int k0 = (kt+1)*32;
            int m = m0 + row;
            if (m < MTOK) {
                float4 a = *(const float4*)(g_y + m*DI + k0 + kq0*4);
                float4 b = *(const float4*)(g_y + (size_t)MTOK*DI + m*DI + k0 + kq0*4);
                pa0 = make_float4(a.x+b.x, a.y+b.y, a.z+b.z, a.w+b.w);
                a = *(const float4*)(g_y + m*DI + k0 + kq0*4 + 4);
                b = *(const float4*)(g_y + (size_t)MTOK*DI + m*DI + k0 + kq0*4 + 4);
                pa1 = make_float4(a.x+b.x, a.y+b.y, a.z+b.z, a.w+b.w);
            } else { pa0 = make_float4(0,0,0,0); pa1 = pa0; }
            pw0 = *(const float4*)(W + (n0 + row)*DI + k0 + kq0*4);
            pw1 = *(const float4*)(W + (n0 + row)*DI + k0 + kq0*4 + 4);
        }
        int buf = kt & 1;
        #pragma unroll
        for (int k = 0; k < 32; k++) {
            float4 bv = *(const float4*)&Ws[buf][k][tx*4];
            float4 a0 = *(const float4*)&As[buf][k][ty*4];
            float av[4] = {a0.x,a0.y,a0.z,a0.w};
            float bw[4] = {bv.x,bv.y,bv.z,bv.w};
            #pragma unroll
            for (int i2 = 0; i2 < 4; i2++)
                #pragma unroll
                for (int j2 = 0; j2 < 4; j2++)
                    acc[i2][j2] = fmaf(av[i2], bw[j2], acc[i2][j2]);
        }
        if (kt + 1 < NK) {
            int bn = buf ^ 1;
            As[bn][kq0*4+0][row]=pa0.x; As[bn][kq0*4+1][row]=pa0.y;
            As[bn][kq0*4+2][row]=pa0.z; As[bn][kq0*4+3][row]=pa0.w;
            As[bn][kq0*4+4][row]=pa1.x; As[bn][kq0*4+5][row]=pa1.y;
            As[bn][kq0*4+6][row]=pa1.z; As[bn][kq0*4+7][row]=pa1.w;
            Ws[bn][kq0*4+0][row]=pw0.x; Ws[bn][kq0*4+1][row]=pw0.y;
            Ws[bn][kq0*4+2][row]=pw0.z; Ws[bn][kq0*4+3][row]=pw0.w;
            Ws[bn][kq0*4+4][row]=pw1.x; Ws[bn][kq0*4+5][row]=pw1.y;
            Ws[bn][kq0*4+6][row]=pw1.z; Ws[bn][kq0*4+7][row]=pw1.w;
        }
        __syncthreads();
    }
    #pragma unroll
    for (int i2 = 0; i2 < 4; i2++) {
        int m = m0 + ty*4 + i2;
        if (m < MTOK) {
            float4 v = make_float4(acc[i2][0], acc[i2][1], acc[i2][2], acc[i2][3]);
            *(float4*)(g_hidden + m*DM + n0 + tx*4) = v;
        }
    }
}

// ---------------- GEMM2 + fused conv/silu + dt epilogue ----------------
// A[m,k] = silu(causal_dwconv(g_xz))  (computed on the fly, written to g_xconv)
// C = g_dbl [3208, 44];  epilogue: g_dt[m,ch] = softplus(dbl[:,0:12] @ dtw^T + dtb)
__global__ void k_gemm2conv(const float* __restrict__ W, const float* __restrict__ cw,
                            const float* __restrict__ cb, const float* __restrict__ dtw,
                            const float* __restrict__ dtb)
{
    __shared__ float As[2][16][68];
    __shared__ float Ws[2][16][68];
    __shared__ float sdbl[64][13];
    __shared__ float sdtw[12][DI];
    int tid = threadIdx.x;
    int m0 = blockIdx.x*64;
    int row = tid >> 2, kq = tid & 3;
    int tx = tid & 15, ty = tid >> 4;

    for (int r = 0; r < 12; r++)
        for (int ch = tid; ch < DI; ch += 256)
            sdtw[r][ch] = dtw[ch*DTRANK + r];

    int m = m0 + row;
    bool mok = (m < 2*MTOK);
    int dirm = (m >= MTOK) ? 1 : 0;
    int rr = mok ? (m - dirm*MTOK) : 0;
    int bb = rr / LSEQ, t = rr % LSEQ;
    int rb = bb*LSEQ;
    int wr = (row < DXP) ? row : 0;

    float4 xzv[4], cwv[4], cbv, pw;

    // fetch tile k0 into regs
    auto fetch = [&](int k0) {
        int k = k0 + kq*4;
        cbv = *(const float4*)(cb + k);
        #pragma unroll
        for (int c2 = 0; c2 < 4; c2++)
            cwv[c2] = *(const float4*)(cw + (k + c2)*4);
        #pragma unroll
        for (int tp = 0; tp < 4; tp++) {
            int tt = dirm ? (t + 3 - tp) : (t - 3 + tp);
            if (mok && tt >= 0 && tt < LSEQ)
                xzv[tp] = *(const float4*)(g_xz + (rb + tt)*2*DI + k);
            else xzv[tp] = make_float4(0,0,0,0);
        }
        pw = *(const float4*)(W + wr*DI + k0 + kq*4);
    };
    // compute conv+silu, write xconv, store smem
    auto stores = [&](int buf, int k0) {
        float xm[4][4];
        #pragma unroll
        for (int tp = 0; tp < 4; tp++) {
            xm[tp][0]=xzv[tp].x; xm[tp][1]=xzv[tp].y; xm[tp][2]=xzv[tp].z; xm[tp][3]=xzv[tp].w;
        }
        float cbm[4] = {cbv.x, cbv.y, cbv.z, cbv.w};
        float sv[4];
        #pragma unroll
        for (int c2 = 0; c2 < 4; c2++) {
            float4 wv = cwv[c2];
            float a = cbm[c2];
            a = fmaf(xm[0][c2], wv.x, a);
            a = fmaf(xm[1][c2], wv.y, a);
            a = fmaf(xm[2][c2], wv.z, a);
            a = fmaf(xm[3][c2], wv.w, a);
            sv[c2] = a / (1.f + __expf(-a));
            As[buf][kq*4+c2][row] = sv[c2];
        }
        if (mok)
            *(float4*)(g_xconv + (size_t)m*DI + k0 + kq*4) = make_float4(sv[0],sv[1],sv[2],sv[3]);
        Ws[buf][kq*4+0][row]=pw.x; Ws[buf][kq*4+1][row]=pw.y;
        Ws[buf][kq*4+2][row]=pw.z; Ws[buf][kq*4+3][row]=pw.w;
    };

    fetch(0); stores(0, 0);
    __syncthreads();

    float acc[4][4] = {};
    const int NK = DI/16;  // 24
    for (int kt = 0; kt < NK; kt++) {
        if (kt + 1 < NK) fetch((kt+1)*16);
        int buf = kt & 1;
        #pragma unroll
        for (int k = 0; k < 16; k++) {
            float4 bv = *(const float4*)&Ws[buf][k][tx*4];
            float4 a0 = *(const float4*)&As[buf][k][ty*4];
            float av[4] = {a0.x,a0.y,a0.z,a0.w};
            float bw[4] = {bv.x,bv.y,bv.z,bv.w};
            #pragma unroll
            for (int i2 = 0; i2 < 4; i2++)
                #pragma unroll
                for (int j2 = 0; j2 < 4; j2++)
                    acc[i2][j2] = fmaf(av[i2], bw[j2], acc[i2][j2]);
        }
        if (kt + 1 < NK) stores((kt & 1) ^ 1, (kt+1)*16);
        __syncthreads();
    }

    // store C (N=44) + sdbl
    #pragma unroll
    for (int i2 = 0; i2 < 4; i2++) {
        int me = m0 + ty*4 + i2;
        if (me < 2*MTOK) {
            if (tx < 11) {
                float4 v = make_float4(acc[i2][0], acc[i2][1], acc[i2][2], acc[i2][3]);
                *(float4*)(g_dbl + (size_t)me*DXP + tx*4) = v;
            }
        }
        if (tx < 3) {
            #pragma unroll
            for (int j2 = 0; j2 < 4; j2++)
                sdbl[ty*4+i2][tx*4+j2] = acc[i2][j2];
        }
    }
    __syncthreads();

    // dt epilogue: 64 rows x 384 ch
    for (int rw = 0; rw < 64; rw++) {
        int me = m0 + rw;
        if (me >= 2*MTOK) break;
        for (int ch = tid; ch < DI; ch += 256) {
            float s = dtb[ch];
            #pragma unroll
            for (int r = 0; r < DTRANK; r++)
                s = fmaf(sdbl[rw][r], sdtw[r][ch], s);
            float sp = (s > 20.f) ? s : log1pf(__expf(s));
            g_dt[(size_t)me*DI + ch] = sp;
        }
    }
}

// ---------------- selective scan: smem partials, no shfl chain ----------------
__global__ void k_scan(const float* __restrict__ Alog_f, const float* __restrict__ Alog_b,
                       const float* __restrict__ Dp)
{
    int cblk = blockIdx.x;  // 0..23
    int b = blockIdx.y;
    int dir = blockIdx.z;
    int tid = threadIdx.x;  // 256
    int warp = tid >> 5, lane = tid & 31;
    int dloc = warp*2 + (lane >> 4);
    int n = lane & 15;
    int d = cblk*16 + dloc;

    __shared__ float sbuf[2][5][CT*16];   // 0=dt 1=xv 2=B 3=C 4=z
    __shared__ float sp[CT][16][20];
    __shared__ float s_Dk[16];
    if (tid < 16) s_Dk[tid] = Dp[cblk*16 + tid];

    const float* Alog = dir ? Alog_b : Alog_f;
    float A = -__expf(Alog[d*DSTATE + n]);
    int rowbase = b*LSEQ;
    int gbase = dir*MTOK + rowbase;

    auto stage = [&](int t0, int bf) {
        if (tid < 96) {                       // 96 f4 loads cover CT*16 floats
            int tt = t0 + (tid >> 2);
            if (tt < LSEQ) {
                int mm = dir ? (LSEQ-1 - tt) : tt;
                int gi = gbase + mm;
                int jq = (tid & 3)*4;
                int idx = (tt - t0)*16 + jq;
                *(float4*)&sbuf[bf][0][idx] = *(const float4*)(g_dt    + (size_t)gi*DI + cblk*16 + jq);
                *(float4*)&sbuf[bf][1][idx] = *(const float4*)(g_xconv + (size_t)gi*DI + cblk*16 + jq);
                *(float4*)&sbuf[bf][2][idx] = *(const float4*)(g_dbl   + (size_t)gi*DXP + DTRANK + jq);
                *(float4*)&sbuf[bf][3][idx] = *(const float4*)(g_dbl   + (size_t)gi*DXP + DTRANK + DSTATE + jq);
                *(float4*)&sbuf[bf][4][idx] = *(const float4*)(g_xz    + (size_t)(rowbase+mm)*2*DI + DI + cblk*16 + jq);
            }
        }
    };

    stage(0, 0);
    __syncthreads();

    float h = 0.f;
    const int nch = (LSEQ + CT - 1)/CT;   // 17
    for (int c = 0; c < nch; c++) {
        int bf = c & 1;
        int tmax = min(CT, LSEQ - c*CT);
        #pragma unroll 4
        for (int k = 0; k < tmax; k++) {
            float dt = sbuf[bf][0][k*16 + dloc];
            float xv = sbuf[bf][1][k*16 + dloc];
            float Bn = sbuf[bf][2][k*16 + n];
            float Cn = sbuf[bf][3][k*16 + n];
            h = fmaf(__expf(dt*A), h, dt*xv*Bn);
            sp[k][dloc][n] = h*Cn;
        }
        __syncthreads();
        if (c + 1 < nch) stage((c+1)*CT, bf ^ 1);
        for (int o = tid; o < tmax*16; o += 256) {
            int k = o >> 4, dd = o & 15;
            float4 p0 = *(const float4*)&sp[k][dd][0];
            float4 p1 = *(const float4*)&sp[k][dd][4];
            float4 p2 = *(const float4*)&sp[k][dd][8];
            float4 p3 = *(const float4*)&sp[k][dd][12];
            float s = ((p0.x+p0.y)+(p0.z+p0.w)) + ((p1.x+p1.y)+(p1.z+p1.w))
                    + ((p2.x+p2.y)+(p2.z+p2.w)) + ((p3.x+p3.y)+(p3.z+p3.w));
            float xvv = sbuf[bf][1][k*16 + dd];
            float z   = sbuf[bf][4][k*16 + dd];
            float y = fmaf(xvv, s_Dk[dd], s);
            int tglob = c*CT + k;
            int mm = dir ? (LSEQ-1 - tglob) : tglob;
            g_y[(size_t)(gbase + mm)*DI + cblk*16 + dd] = y * (z / (1.f + __expf(-z)));
        }
        __syncthreads();
    }
}

// ---------------- final norm + head (cls token only) ----------------
__global__ void k_head(const float* __restrict__ nfw, const float* __restrict__ hw,
                       const float* __restrict__ hb, float* __restrict__ out)
{
    int b = blockIdx.x;
    int tid = threadIdx.x; // 192
    __shared__ float rn[DM];
    __shared__ float red[6];
    int m = b*LSEQ;
    float v = g_residual[m*DM + tid] + g_hidden[m*DM + tid];
    float ss = v*v;
    #pragma unroll
    for (int o = 16; o; o >>= 1) ss += __shfl_xor_sync(~0u, ss, o);
    if ((tid & 31) == 0) red[tid >> 5] = ss;
    __syncthreads();
    float tot = red[0] + red[1] + red[2] + red[3] + red[4] + red[5];
    float rstd = rsqrtf(tot*(1.f/DM) + 1e-5f);
    rn[tid] = v*rstd*nfw[tid];
    __syncthreads();
    if (tid < 22) {
        float s = hb[tid];
        const float* wr = hw + tid*DM;
        #pragma unroll 4
        for (int k = 0; k < DM; k++) s = fmaf(rn[k], wr[k], s);
        out[b*22 + tid] = s;
    }
}

// ---------------- launcher ----------------
extern "C" void kernel_launch(void* const* d_in, const int* in_sizes, int n_in,
                              void* d_out, int out_size)
{
    const float* x         = (const float*)d_in[0];
    const float* pe_w      = (const float*)d_in[1];
    const float* pe_b      = (const float*)d_in[2];
    const float* cls_token = (const float*)d_in[3];
    const float* pos_embed = (const float*)d_in[4];
    const float* norm_w    = (const float*)d_in[5];
    const float* in_proj_w = (const float*)d_in[6];
    const float* cw        = (const float*)d_in[7];
    const float* cb        = (const float*)d_in[8];
    const float* xproj_w   = (const float*)d_in[9];
    const float* dtproj_w  = (const float*)d_in[10];
    const float* dtproj_b  = (const float*)d_in[11];
    const float* A_log     = (const float*)d_in[12];
    const float* A_b_log   = (const float*)d_in[13];
    const float* Dp        = (const float*)d_in[14];
    const float* outproj_w = (const float*)d_in[15];
    const float* norm_f_w  = (const float*)d_in[16];
    const float* head_w    = (const float*)d_in[17];
    const float* head_b    = (const float*)d_in[18];
    float* out = (float*)d_out;

    k_patch<<<dim3(400, NB), 256>>>(x, pe_w, pe_b, cls_token, pos_embed);

    for (int l = 0; l < DEPTH; l++) {
        k_prenorm<<<(MTOK + 7)/8, 256>>>(norm_w + l*DM);
        k_gemm0<<<dim3((MTOK + 127)/128, (2*DI)/64), 256>>>(in_proj_w + (size_t)l*2*DI*DM);
        k_gemm2conv<<<dim3((2*MTOK + 63)/64, 1), 256>>>(xproj_w + (size_t)l*DXP*DI,
                                                        cw + l*DI*DCONV, cb + l*DI,
                                                        dtproj_w + (size_t)l*DI*DTRANK,
                                                        dtproj_b + l*DI);
        k_scan<<<dim3(DI/16, NB, 2), 256>>>(A_log + (size_t)l*DI*DSTATE,
                                            A_b_log + (size_t)l*DI*DSTATE,
                                            Dp + l*DI);
        k_gemm1<<<dim3((MTOK + 63)/64, DM/64), 256>>>(outproj_w + (size_t)l*DM*DI);
    }

    k_head<<<NB, DM>>>(norm_f_w, head_w, head_b, out);
}

// round 7
// speedup vs baseline: 3.4338x; 1.1462x over previous
#include <cuda_runtime.h>
#include <cuda_bf16.h>
#include <math.h>

// ---------------- Model constants ----------------
#define DEPTH   24
#define DM      192       // d_model
#define DI      384       // d_inner
#define DSTATE  16
#define DTRANK  12
#define DCONV   4
#define LSEQ    401       // NP+1
#define NB      4         // batch
#define MTOK    (NB*LSEQ) // 1604
#define DXP     (DTRANK + 2*DSTATE) // 44
#define CT      24        // scan chunk length

// ---------------- Scratch (device globals; no allocation) ----------------
__device__ float g_hidden  [MTOK*DM];
__device__ float g_residual[MTOK*DM];
__device__ float g_hnorm   [MTOK*DM];
__device__ float g_xz      [MTOK*2*DI];       // [:,0:384]=xx, [:,384:768]=z
__device__ float g_xconv   [2*MTOK*DI];       // per dir, silu(conv(x))
__device__ float g_dbl     [2*MTOK*DXP];      // xproj out [dt_r(12), B(16), C(16)]
__device__ float g_dt      [2*MTOK*DI];       // softplus(dt)
__device__ float g_y       [2*MTOK*DI];       // gated outputs per dir

// ---------------- Patch embed + cls + pos ----------------
__global__ void k_patch(const float* __restrict__ x, const float* __restrict__ pe_w,
                        const float* __restrict__ pe_b, const float* __restrict__ cls,
                        const float* __restrict__ pos)
{
    int p = blockIdx.x;          // 0..399
    int b = blockIdx.y;          // 0..3
    int tid = threadIdx.x;       // 256
    __shared__ float sp[256];
    int ph = p / 200, pw = p % 200;
    int i = tid >> 4, j = tid & 15;
    sp[tid] = x[b*32*3200 + (ph*16 + i)*3200 + pw*16 + j];
    __syncthreads();
    if (tid < DM) {
        int c = tid;
        const float* w = pe_w + c*256;
        float acc = pe_b[c];
        #pragma unroll 8
        for (int k = 0; k < 256; k++) acc += sp[k]*w[k];
        int t = p + 1;
        float v = acc + pos[t*DM + c];
        int m = b*LSEQ + t;
        g_hidden[m*DM + c] = v;
        g_residual[m*DM + c] = v;
        if (p == 0) {
            float cv = cls[c] + pos[c];
            int m0 = b*LSEQ;
            g_hidden[m0*DM + c] = cv;
            g_residual[m0*DM + c] = cv;
        }
    }
}

// ---------------- residual += hidden ; hnorm = rmsnorm(residual)*w ----------------
__global__ void k_prenorm(const float* __restrict__ norm_w)
{
    int warp = threadIdx.x >> 5, lane = threadIdx.x & 31;
    int m = blockIdx.x*8 + warp;
    if (m >= MTOK) return;
    float r[6]; float ss = 0.f;
    #pragma unroll
    for (int u = 0; u < 6; u++) {
        int c = lane + u*32;
        float v = g_residual[m*DM + c] + g_hidden[m*DM + c];
        r[u] = v; ss += v*v;
        g_residual[m*DM + c] = v;
    }
    #pragma unroll
    for (int o = 16; o; o >>= 1) ss += __shfl_xor_sync(~0u, ss, o);
    float rstd = rsqrtf(ss*(1.f/DM) + 1e-5f);
    #pragma unroll
    for (int u = 0; u < 6; u++) {
        int c = lane + u*32;
        g_hnorm[m*DM + c] = r[u]*rstd*norm_w[c];
    }
}

// ---------------- GEMM0: g_xz[1604,768] = g_hnorm[1604,192] @ W[768,192]^T ----------------
// 128x64 tile, 256 thr, 8x4 acc, KT=16, double-buffered
__global__ void k_gemm0(const float* __restrict__ W)
{
    __shared__ float As[2][16][132];
    __shared__ float Ws[2][16][68];
    int tid = threadIdx.x;
    int m0 = blockIdx.x*128, n0 = blockIdx.y*64;
    int arow = tid >> 1, akq = (tid & 1)*2;
    int wrow = tid >> 2, wkq = tid & 3;
    int tx = tid & 15, ty = tid >> 4;
    float4 pa0, pa1, pw;

    {
        int m = m0 + arow;
        if (m < MTOK) {
            pa0 = *(const float4*)(g_hnorm + m*DM + akq*4);
            pa1 = *(const float4*)(g_hnorm + m*DM + akq*4 + 4);
        } else { pa0 = make_float4(0,0,0,0); pa1 = pa0; }
        pw = *(const float4*)(W + (n0 + wrow)*DM + wkq*4);
        As[0][akq*4+0][arow]=pa0.x; As[0][akq*4+1][arow]=pa0.y;
        As[0][akq*4+2][arow]=pa0.z; As[0][akq*4+3][arow]=pa0.w;
        As[0][akq*4+4][arow]=pa1.x; As[0][akq*4+5][arow]=pa1.y;
        As[0][akq*4+6][arow]=pa1.z; As[0][akq*4+7][arow]=pa1.w;
        Ws[0][wkq*4+0][wrow]=pw.x;  Ws[0][wkq*4+1][wrow]=pw.y;
        Ws[0][wkq*4+2][wrow]=pw.z;  Ws[0][wkq*4+3][wrow]=pw.w;
    }
    __syncthreads();

    float acc[8][4] = {};
    const int NK = DM/16;  // 12
    for (int kt = 0; kt < NK; kt++) {
        if (kt + 1 < NK) {
            int k0 = (kt+1)*16;
            int m = m0 + arow;
            if (m < MTOK) {
                pa0 = *(const float4*)(g_hnorm + m*DM + k0 + akq*4);
                pa1 = *(const float4*)(g_hnorm + m*DM + k0 + akq*4 + 4);
            } else { pa0 = make_float4(0,0,0,0); pa1 = pa0; }
            pw = *(const float4*)(W + (n0 + wrow)*DM + k0 + wkq*4);
        }
        int buf = kt & 1;
        #pragma unroll
        for (int k = 0; k < 16; k++) {
            float4 bv = *(const float4*)&Ws[buf][k][tx*4];
            float4 a0 = *(const float4*)&As[buf][k][ty*8];
            float4 a1 = *(const float4*)&As[buf][k][ty*8+4];
            float av[8] = {a0.x,a0.y,a0.z,a0.w,a1.x,a1.y,a1.z,a1.w};
            float bw[4] = {bv.x,bv.y,bv.z,bv.w};
            #pragma unroll
            for (int i2 = 0; i2 < 8; i2++)
                #pragma unroll
                for (int j2 = 0; j2 < 4; j2++)
                    acc[i2][j2] = fmaf(av[i2], bw[j2], acc[i2][j2]);
        }
        if (kt + 1 < NK) {
            int bn = buf ^ 1;
            As[bn][akq*4+0][arow]=pa0.x; As[bn][akq*4+1][arow]=pa0.y;
            As[bn][akq*4+2][arow]=pa0.z; As[bn][akq*4+3][arow]=pa0.w;
            As[bn][akq*4+4][arow]=pa1.x; As[bn][akq*4+5][arow]=pa1.y;
            As[bn][akq*4+6][arow]=pa1.z; As[bn][akq*4+7][arow]=pa1.w;
            Ws[bn][wkq*4+0][wrow]=pw.x;  Ws[bn][wkq*4+1][wrow]=pw.y;
            Ws[bn][wkq*4+2][wrow]=pw.z;  Ws[bn][wkq*4+3][wrow]=pw.w;
        }
        __syncthreads();
    }
    #pragma unroll
    for (int i2 = 0; i2 < 8; i2++) {
        int m = m0 + ty*8 + i2;
        if (m < MTOK) {
            float4 v = make_float4(acc[i2][0], acc[i2][1], acc[i2][2], acc[i2][3]);
            *(float4*)(g_xz + m*2*DI + n0 + tx*4) = v;
        }
    }
}

// ---------------- GEMM1: g_hidden[1604,192] = (y0+y1)[1604,384] @ W[192,384]^T ----------------
__global__ void k_gemm1(const float* __restrict__ W)
{
    __shared__ float As[2][32][68];
    __shared__ float Ws[2][32][68];
    int tid = threadIdx.x;
    int m0 = blockIdx.x*64, n0 = blockIdx.y*64;
    int row = tid >> 2, kq0 = (tid & 3)*2;
    int tx = tid & 15, ty = tid >> 4;
    float4 pa0, pa1, pw0, pw1;

    {
        int m = m0 + row;
        if (m < MTOK) {
            float4 a = *(const float4*)(g_y + m*DI + kq0*4);
            float4 b = *(const float4*)(g_y + (size_t)MTOK*DI + m*DI + kq0*4);
            pa0 = make_float4(a.x+b.x, a.y+b.y, a.z+b.z, a.w+b.w);
            a = *(const float4*)(g_y + m*DI + kq0*4 + 4);
            b = *(const float4*)(g_y + (size_t)MTOK*DI + m*DI + kq0*4 + 4);
            pa1 = make_float4(a.x+b.x, a.y+b.y, a.z+b.z, a.w+b.w);
        } else { pa0 = make_float4(0,0,0,0); pa1 = pa0; }
        pw0 = *(const float4*)(W + (n0 + row)*DI + kq0*4);
        pw1 = *(const float4*)(W + (n0 + row)*DI + kq0*4 + 4);
        As[0][kq0*4+0][row]=pa0.x; As[0][kq0*4+1][row]=pa0.y;
        As[0][kq0*4+2][row]=pa0.z; As[0][kq0*4+3][row]=pa0.w;
        As[0][kq0*4+4][row]=pa1.x; As[0][kq0*4+5][row]=pa1.y;
        As[0][kq0*4+6][row]=pa1.z; As[0][kq0*4+7][row]=pa1.w;
        Ws[0][kq0*4+0][row]=pw0.x; Ws[0][kq0*4+1][row]=pw0.y;
        Ws[0][kq0*4+2][row]=pw0.z; Ws[0][kq0*4+3][row]=pw0.w;
        Ws[0][kq0*4+4][row]=pw1.x; Ws[0][kq0*4+5][row]=pw1.y;
        Ws[0][kq0*4+6][row]=pw1.z; Ws[0][kq0*4+7][row]=pw1.w;
    }
    __syncthreads();

    float acc[4][4] = {};
    const int NK = DI/32;  // 12
    for (int kt = 0; kt < NK; kt++) {
        if (kt + 1 < NK) {
            int k0 = (kt+1)*32;
            int m = m0 + row;
            if (m < MTOK) {
                float4 a = *(const float4*)(g_y + m*DI + k0 + kq0*4);
                float4 b = *(const float4*)(g_y + (size_t)MTOK*DI + m*DI + k0 + kq0*4);
                pa0 = make_float4(a.x+b.x, a.y+b.y, a.z+b.z, a.w+b.w);
                a = *(const float4*)(g_y + m*DI + k0 + kq0*4 + 4);
                b = *(const float4*)(g_y + (size_t)MTOK*DI + m*DI + k0 + kq0*4 + 4);
                pa1 = make_float4(a.x+b.x, a.y+b.y, a.z+b.z, a.w+b.w);
            } else { pa0 = make_float4(0,0,0,0); pa1 = pa0; }
            pw0 = *(const float4*)(W + (n0 + row)*DI + k0 + kq0*4);
            pw1 = *(const float4*)(W + (n0 + row)*DI + k0 + kq0*4 + 4);
        }
        int buf = kt & 1;
        #pragma unroll
        for (int k = 0; k < 32; k++) {
            float4 bv = *(const float4*)&Ws[buf][k][tx*4];
            float4 a0 = *(const float4*)&As[buf][k][ty*4];
            float av[4] = {a0.x,a0.y,a0.z,a0.w};
            float bw[4] = {bv.x,bv.y,bv.z,bv.w};
            #pragma unroll
            for (int i2 = 0; i2 < 4; i2++)
                #pragma unroll
                for (int j2 = 0; j2 < 4; j2++)
                    acc[i2][j2] = fmaf(av[i2], bw[j2], acc[i2][j2]);
        }
        if (kt + 1 < NK) {
            int bn = buf ^ 1;
            As[bn][kq0*4+0][row]=pa0.x; As[bn][kq0*4+1][row]=pa0.y;
            As[bn][kq0*4+2][row]=pa0.z; As[bn][kq0*4+3][row]=pa0.w;
            As[bn][kq0*4+4][row]=pa1.x; As[bn][kq0*4+5][row]=pa1.y;
            As[bn][kq0*4+6][row]=pa1.z; As[bn][kq0*4+7][row]=pa1.w;
            Ws[bn][kq0*4+0][row]=pw0.x; Ws[bn][kq0*4+1][row]=pw0.y;
            Ws[bn][kq0*4+2][row]=pw0.z; Ws[bn][kq0*4+3][row]=pw0.w;
            Ws[bn][kq0*4+4][row]=pw1.x; Ws[bn][kq0*4+5][row]=pw1.y;
            Ws[bn][kq0*4+6][row]=pw1.z; Ws[bn][kq0*4+7][row]=pw1.w;
        }
        __syncthreads();
    }
    #pragma unroll
    for (int i2 = 0; i2 < 4; i2++) {
        int m = m0 + ty*4 + i2;
        if (m < MTOK) {
            float4 v = make_float4(acc[i2][0], acc[i2][1], acc[i2][2], acc[i2][3]);
            *(float4*)(g_hidden + m*DM + n0 + tx*4) = v;
        }
    }
}

// ---------------- causal dwconv + silu, both dirs ----------------
__global__ void k_conv(const float* __restrict__ cw, const float* __restrict__ cb)
{
    int t = blockIdx.x, b = blockIdx.y;
    int d = threadIdx.x;              // 384
    float w0 = cw[d*4+0], w1 = cw[d*4+1], w2 = cw[d*4+2], w3 = cw[d*4+3];
    float bias = cb[d];
    int rowbase = b*LSEQ;
    float accf = bias;
    if (t-3 >= 0) accf = fmaf(g_xz[(rowbase + t-3)*2*DI + d], w0, accf);
    if (t-2 >= 0) accf = fmaf(g_xz[(rowbase + t-2)*2*DI + d], w1, accf);
    if (t-1 >= 0) accf = fmaf(g_xz[(rowbase + t-1)*2*DI + d], w2, accf);
    accf = fmaf(g_xz[(rowbase + t)*2*DI + d], w3, accf);
    g_xconv[(rowbase + t)*DI + d] = accf / (1.f + __expf(-accf));
    float accb = bias;
    if (t+3 <= LSEQ-1) accb = fmaf(g_xz[(rowbase + t+3)*2*DI + d], w0, accb);
    if (t+2 <= LSEQ-1) accb = fmaf(g_xz[(rowbase + t+2)*2*DI + d], w1, accb);
    if (t+1 <= LSEQ-1) accb = fmaf(g_xz[(rowbase + t+1)*2*DI + d], w2, accb);
    accb = fmaf(g_xz[(rowbase + t)*2*DI + d], w3, accb);
    g_xconv[(MTOK + rowbase + t)*DI + d] = accb / (1.f + __expf(-accb));
}

// ---------------- GEMM2: g_dbl[3208,44] = g_xconv[3208,384] @ W[44,384]^T ----------------
// 32-row tiles -> grid 101; 192 thr; per thread 2x4 outputs
__global__ void k_gemm2(const float* __restrict__ W)
{
    __shared__ float As[32][34];   // [k][m]
    __shared__ float Ws[32][52];   // [k][n] (48 padded)
    int tid = threadIdx.x;         // 192
    int m0 = blockIdx.x*32;
    int ty = tid / 12, tx = tid % 12;  // ty 0..15, tx 0..11
    float acc[2][4] = {};
    for (int k0 = 0; k0 < DI; k0 += 32) {
        for (int i = tid; i < 256; i += 192) {
            int mr = i >> 3, kq = i & 7;
            int m = m0 + mr;
            float4 v = make_float4(0,0,0,0);
            if (m < 2*MTOK) v = *(const float4*)(g_xconv + (size_t)m*DI + k0 + kq*4);
            As[kq*4+0][mr]=v.x; As[kq*4+1][mr]=v.y; As[kq*4+2][mr]=v.z; As[kq*4+3][mr]=v.w;
        }
        for (int i = tid; i < 384; i += 192) {
            int nr = i >> 3, kq = i & 7;
            float4 v = make_float4(0,0,0,0);
            if (nr < DXP) v = *(const float4*)(W + nr*DI + k0 + kq*4);
            Ws[kq*4+0][nr]=v.x; Ws[kq*4+1][nr]=v.y; Ws[kq*4+2][nr]=v.z; Ws[kq*4+3][nr]=v.w;
        }
        __syncthreads();
        #pragma unroll
        for (int k = 0; k < 32; k++) {
            float2 a = *(const float2*)&As[k][ty*2];
            float4 w4 = *(const float4*)&Ws[k][tx*4];
            acc[0][0]=fmaf(a.x,w4.x,acc[0][0]); acc[0][1]=fmaf(a.x,w4.y,acc[0][1]);
            acc[0][2]=fmaf(a.x,w4.z,acc[0][2]); acc[0][3]=fmaf(a.x,w4.w,acc[0][3]);
            acc[1][0]=fmaf(a.y,w4.x,acc[1][0]); acc[1][1]=fmaf(a.y,w4.y,acc[1][1]);
            acc[1][2]=fmaf(a.y,w4.z,acc[1][2]); acc[1][3]=fmaf(a.y,w4.w,acc[1][3]);
        }
        __syncthreads();
    }
    if (tx < 11) {
        #pragma unroll
        for (int i2 = 0; i2 < 2; i2++) {
            int m = m0 + ty*2 + i2;
            if (m < 2*MTOK) {
                float4 v = make_float4(acc[i2][0], acc[i2][1], acc[i2][2], acc[i2][3]);
                *(float4*)(g_dbl + (size_t)m*DXP + tx*4) = v;
            }
        }
    }
}

// ---------------- dt projection: g_dt[3208,384] = softplus(dbl[:,0:12] @ dtw^T + dtb) ----------------
__global__ void k_dt(const float* __restrict__ dtw, const float* __restrict__ dtb)
{
    int m0 = blockIdx.x*8;         // 401 blocks * 8 = 3208 exactly
    int ch = threadIdx.x;          // 384
    __shared__ float sdb[8][12];
    if (ch < 96) {
        int r = ch / 12, j = ch % 12;
        sdb[r][j] = g_dbl[(size_t)(m0 + r)*DXP + j];
    }
    float wr[12];
    #pragma unroll
    for (int r = 0; r < 12; r++) wr[r] = dtw[ch*DTRANK + r];
    float bias = dtb[ch];
    __syncthreads();
    #pragma unroll
    for (int q = 0; q < 8; q++) {
        float s = bias;
        #pragma unroll
        for (int r = 0; r < 12; r++) s = fmaf(sdb[q][r], wr[r], s);
        float sp = (s > 20.f) ? s : log1pf(__expf(s));
        g_dt[(size_t)(m0 + q)*DI + ch] = sp;
    }
}

// ---------------- selective scan: smem partials, no shfl chain ----------------
__global__ void k_scan(const float* __restrict__ Alog_f, const float* __restrict__ Alog_b,
                       const float* __restrict__ Dp)
{
    int cblk = blockIdx.x;  // 0..23
    int b = blockIdx.y;
    int dir = blockIdx.z;
    int tid = threadIdx.x;  // 256
    int warp = tid >> 5, lane = tid & 31;
    int dloc = warp*2 + (lane >> 4);
    int n = lane & 15;
    int d = cblk*16 + dloc;

    __shared__ float sbuf[2][5][CT*16];   // 0=dt 1=xv 2=B 3=C 4=z
    __shared__ float sp[CT][16][20];
    __shared__ float s_Dk[16];
    if (tid < 16) s_Dk[tid] = Dp[cblk*16 + tid];

    const float* Alog = dir ? Alog_b : Alog_f;
    float A = -__expf(Alog[d*DSTATE + n]);
    int rowbase = b*LSEQ;
    int gbase = dir*MTOK + rowbase;

    auto stage = [&](int t0, int bf) {
        if (tid < 96) {
            int tt = t0 + (tid >> 2);
            if (tt < LSEQ) {
                int mm = dir ? (LSEQ-1 - tt) : tt;
                int gi = gbase + mm;
                int jq = (tid & 3)*4;
                int idx = (tt - t0)*16 + jq;
                *(float4*)&sbuf[bf][0][idx] = *(const float4*)(g_dt    + (size_t)gi*DI + cblk*16 + jq);
                *(float4*)&sbuf[bf][1][idx] = *(const float4*)(g_xconv + (size_t)gi*DI + cblk*16 + jq);
                *(float4*)&sbuf[bf][2][idx] = *(const float4*)(g_dbl   + (size_t)gi*DXP + DTRANK + jq);
                *(float4*)&sbuf[bf][3][idx] = *(const float4*)(g_dbl   + (size_t)gi*DXP + DTRANK + DSTATE + jq);
                *(float4*)&sbuf[bf][4][idx] = *(const float4*)(g_xz    + (size_t)(rowbase+mm)*2*DI + DI + cblk*16 + jq);
            }
        }
    };

    stage(0, 0);
    __syncthreads();

    float h = 0.f;
    const int nch = (LSEQ + CT - 1)/CT;   // 17
    for (int c = 0; c < nch; c++) {
        int bf = c & 1;
        int tmax = min(CT, LSEQ - c*CT);
        #pragma unroll 4
        for (int k = 0; k < tmax; k++) {
            float dt = sbuf[bf][0][k*16 + dloc];
            float xv = sbuf[bf][1][k*16 + dloc];
            float Bn = sbuf[bf][2][k*16 + n];
            float Cn = sbuf[bf][3][k*16 + n];
            h = fmaf(__expf(dt*A), h, dt*xv*Bn);
            sp[k][dloc][n] = h*Cn;
        }
        __syncthreads();
        if (c + 1 < nch) stage((c+1)*CT, bf ^ 1);
        for (int o = tid; o < tmax*16; o += 256) {
            int k = o >> 4, dd = o & 15;
            float4 p0 = *(const float4*)&sp[k][dd][0];
            float4 p1 = *(const float4*)&sp[k][dd][4];
            float4 p2 = *(const float4*)&sp[k][dd][8];
            float4 p3 = *(const float4*)&sp[k][dd][12];
            float s = ((p0.x+p0.y)+(p0.z+p0.w)) + ((p1.x+p1.y)+(p1.z+p1.w))
                    + ((p2.x+p2.y)+(p2.z+p2.w)) + ((p3.x+p3.y)+(p3.z+p3.w));
            float xvv = sbuf[bf][1][k*16 + dd];
            float z   = sbuf[bf][4][k*16 + dd];
            float y = fmaf(xvv, s_Dk[dd], s);
            int tglob = c*CT + k;
            int mm = dir ? (LSEQ-1 - tglob) : tglob;
            g_y[(size_t)(gbase + mm)*DI + cblk*16 + dd] = y * (z / (1.f + __expf(-z)));
        }
        __syncthreads();
    }
}

// ---------------- final norm + head (cls token only) ----------------
__global__ void k_head(const float* __restrict__ nfw, const float* __restrict__ hw,
                       const float* __restrict__ hb, float* __restrict__ out)
{
    int b = blockIdx.x;
    int tid = threadIdx.x; // 192
    __shared__ float rn[DM];
    __shared__ float red[6];
    int m = b*LSEQ;
    float v = g_residual[m*DM + tid] + g_hidden[m*DM + tid];
    float ss = v*v;
    #pragma unroll
    for (int o = 16; o; o >>= 1) ss += __shfl_xor_sync(~0u, ss, o);
    if ((tid & 31) == 0) red[tid >> 5] = ss;
    __syncthreads();
    float tot = red[0] + red[1] + red[2] + red[3] + red[4] + red[5];
    float rstd = rsqrtf(tot*(1.f/DM) + 1e-5f);
    rn[tid] = v*rstd*nfw[tid];
    __syncthreads();
    if (tid < 22) {
        float s = hb[tid];
        const float* wr = hw + tid*DM;
        #pragma unroll 4
        for (int k = 0; k < DM; k++) s = fmaf(rn[k], wr[k], s);
        out[b*22 + tid] = s;
    }
}

// ---------------- launcher ----------------
extern "C" void kernel_launch(void* const* d_in, const int* in_sizes, int n_in,
                              void* d_out, int out_size)
{
    const float* x         = (const float*)d_in[0];
    const float* pe_w      = (const float*)d_in[1];
    const float* pe_b      = (const float*)d_in[2];
    const float* cls_token = (const float*)d_in[3];
    const float* pos_embed = (const float*)d_in[4];
    const float* norm_w    = (const float*)d_in[5];
    const float* in_proj_w = (const float*)d_in[6];
    const float* cw        = (const float*)d_in[7];
    const float* cb        = (const float*)d_in[8];
    const float* xproj_w   = (const float*)d_in[9];
    const float* dtproj_w  = (const float*)d_in[10];
    const float* dtproj_b  = (const float*)d_in[11];
    const float* A_log     = (const float*)d_in[12];
    const float* A_b_log   = (const float*)d_in[13];
    const float* Dp        = (const float*)d_in[14];
    const float* outproj_w = (const float*)d_in[15];
    const float* norm_f_w  = (const float*)d_in[16];
    const float* head_w    = (const float*)d_in[17];
    const float* head_b    = (const float*)d_in[18];
    float* out = (float*)d_out;

    k_patch<<<dim3(400, NB), 256>>>(x, pe_w, pe_b, cls_token, pos_embed);

    for (int l = 0; l < DEPTH; l++) {
        k_prenorm<<<(MTOK + 7)/8, 256>>>(norm_w + l*DM);
        k_gemm0<<<dim3((MTOK + 127)/128, (2*DI)/64), 256>>>(in_proj_w + (size_t)l*2*DI*DM);
        k_conv<<<dim3(LSEQ, NB), DI>>>(cw + l*DI*DCONV, cb + l*DI);
        k_gemm2<<<(2*MTOK + 31)/32, 192>>>(xproj_w + (size_t)l*DXP*DI);
        k_dt<<<2*MTOK/8, DI>>>(dtproj_w + (size_t)l*DI*DTRANK, dtproj_b + l*DI);
        k_scan<<<dim3(DI/16, NB, 2), 256>>>(A_log + (size_t)l*DI*DSTATE,
                                            A_b_log + (size_t)l*DI*DSTATE,
                                            Dp + l*DI);
        k_gemm1<<<dim3((MTOK + 63)/64, DM/64), 256>>>(outproj_w + (size_t)l*DM*DI);
    }

    k_head<<<NB, DM>>>(norm_f_w, head_w, head_b, out);
}